// round 10
// baseline (speedup 1.0000x reference)
#include <cuda_runtime.h>
#include <cstdint>
#include <math.h>

// ---------------------------------------------------------------------------
// topk cross-entropy: mean of top-70% per-row NLL losses.
//   loss[i] = log(sum_c exp(x[i,c])) - x[i, target[i]]   (>= 0)
// 4096-bin radix histogram (keys = top16 float bits, window [2^-7, 2^25)),
// privatized per block in smem, + scalar lo/hi overflow accumulators.
// One selection kernel does the hierarchical suffix scan, emits the mean,
// and re-zeroes all state for the next invocation (2 kernels total).
// Boundary bin credited proportionally (bin rel. width 2^-7 -> ~4e-5 err).
// ---------------------------------------------------------------------------

#define FULLMASK 0xFFFFFFFFu
#define WIN_LO   0x3C00u          // key of 2^-7
#define WIN_BINS 4096

__device__ unsigned g_cnt[WIN_BINS];
__device__ float    g_sum[WIN_BINS];
__device__ unsigned g_loCnt, g_hiCnt;
__device__ float    g_loSum, g_hiSum;

__device__ __forceinline__ float warp_sum(float v) {
    #pragma unroll
    for (int o = 16; o; o >>= 1) v += __shfl_xor_sync(FULLMASK, v, o);
    return v;
}

// inclusive suffix scan within a warp (sum over lanes >= lane)
__device__ __forceinline__ void warp_suffix(unsigned& c, float& s) {
    int lane = threadIdx.x & 31;
    #pragma unroll
    for (int o = 1; o < 32; o <<= 1) {
        unsigned tc = __shfl_down_sync(FULLMASK, c, o);
        float    ts = __shfl_down_sync(FULLMASK, s, o);
        if (lane + o < 32) { c += tc; s += ts; }
    }
}

__device__ __forceinline__ float row_exp_sum(float4 v) {
    return __expf(v.x) + __expf(v.y) + __expf(v.z) + __expf(v.w);
}

__device__ __forceinline__ float sel4(float4 v, int sub) {
    return sub == 0 ? v.x : sub == 1 ? v.y : sub == 2 ? v.z : v.w;
}

// K1: persistent, 4 rows per warp per iteration (MLP=4), max-free LSE,
//     shared-memory privatized histogram (4096-bin window + lo/hi scalars).
__global__ void __launch_bounds__(512, 2)
k_loss128(const float4* __restrict__ x,
          const long long* __restrict__ tgt,
          int N, int totalWarps) {
    __shared__ unsigned scnt[WIN_BINS];
    __shared__ float    ssum[WIN_BINS];
    __shared__ unsigned sLoC, sHiC;
    __shared__ float    sLoS, sHiS;

    int tid  = threadIdx.x;
    int gw   = (blockIdx.x * blockDim.x + tid) >> 5;
    int lane = tid & 31;

    #pragma unroll
    for (int b = tid; b < WIN_BINS; b += 512) { scnt[b] = 0u; ssum[b] = 0.0f; }
    if (tid == 0) { sLoC = 0u; sHiC = 0u; sLoS = 0.0f; sHiS = 0.0f; }
    __syncthreads();

    for (int row0 = gw * 4; row0 < N; row0 += totalWarps * 4) {
        float4 v0 = __ldg(&x[(size_t)(row0 + 0) * 32 + lane]);
        float4 v1 = __ldg(&x[(size_t)(row0 + 1) * 32 + lane]);
        float4 v2 = __ldg(&x[(size_t)(row0 + 2) * 32 + lane]);
        float4 v3 = __ldg(&x[(size_t)(row0 + 3) * 32 + lane]);
        int t0 = (int)__ldg(&tgt[row0 + 0]);
        int t1 = (int)__ldg(&tgt[row0 + 1]);
        int t2 = (int)__ldg(&tgt[row0 + 2]);
        int t3 = (int)__ldg(&tgt[row0 + 3]);

        float s0 = row_exp_sum(v0);
        float s1 = row_exp_sum(v1);
        float s2 = row_exp_sum(v2);
        float s3 = row_exp_sum(v3);
        s0 = warp_sum(s0); s1 = warp_sum(s1); s2 = warp_sum(s2); s3 = warp_sum(s3);

        float xt0 = __shfl_sync(FULLMASK, sel4(v0, t0 & 3), t0 >> 2);
        float xt1 = __shfl_sync(FULLMASK, sel4(v1, t1 & 3), t1 >> 2);
        float xt2 = __shfl_sync(FULLMASK, sel4(v2, t2 & 3), t2 >> 2);
        float xt3 = __shfl_sync(FULLMASK, sel4(v3, t3 & 3), t3 >> 2);

        float l0 = fmaxf(__logf(s0) - xt0, 0.0f);
        float l1 = fmaxf(__logf(s1) - xt1, 0.0f);
        float l2 = fmaxf(__logf(s2) - xt2, 0.0f);
        float l3 = fmaxf(__logf(s3) - xt3, 0.0f);

        if (lane < 4) {
            float L = lane == 0 ? l0 : lane == 1 ? l1 : lane == 2 ? l2 : l3;
            unsigned key = __float_as_uint(L) >> 16;
            unsigned w   = key - WIN_LO;
            if (w < WIN_BINS) {               // fast path: smem private bins
                atomicAdd(&scnt[w], 1u);
                atomicAdd(&ssum[w], L);
            } else if (key < WIN_LO) {        // tiny losses
                atomicAdd(&sLoC, 1u); atomicAdd(&sLoS, L);
            } else {                          // huge losses
                atomicAdd(&sHiC, 1u); atomicAdd(&sHiS, L);
            }
        }
    }

    __syncthreads();
    // flush: one global RED per nonzero private bin + scalars
    for (int b = tid; b < WIN_BINS; b += 512) {
        unsigned c = scnt[b];
        if (c) {
            atomicAdd(&g_cnt[b], c);
            atomicAdd(&g_sum[b], ssum[b]);
        }
    }
    if (tid == 0) {
        if (sLoC) { atomicAdd(&g_loCnt, sLoC); atomicAdd(&g_loSum, sLoS); }
        if (sHiC) { atomicAdd(&g_hiCnt, sHiC); atomicAdd(&g_hiSum, sHiS); }
    }
}

// Generic fallback (C != 128 or N % 4 != 0) — safety only.
__global__ void k_loss_generic(const float* __restrict__ x,
                               const long long* __restrict__ tgt, int N, int C) {
    int r = blockIdx.x * blockDim.x + threadIdx.x;
    if (r >= N) return;
    const float* row = x + (size_t)r * C;
    float m = -INFINITY;
    for (int c = 0; c < C; c++) m = fmaxf(m, row[c]);
    float s = 0.0f;
    for (int c = 0; c < C; c++) s += __expf(row[c] - m);
    float loss = fmaxf(m + __logf(s) - row[(int)tgt[r]], 0.0f);
    unsigned key = __float_as_uint(loss) >> 16;
    unsigned w   = key - WIN_LO;
    if (w < WIN_BINS) { atomicAdd(&g_cnt[w], 1u); atomicAdd(&g_sum[w], loss); }
    else if (key < WIN_LO) { atomicAdd(&g_loCnt, 1u); atomicAdd(&g_loSum, loss); }
    else                   { atomicAdd(&g_hiCnt, 1u); atomicAdd(&g_hiSum, loss); }
}

// K2: single block, 1024 threads, 4 bins/thread. Hierarchical suffix scan
//     picks the threshold bin, emits the mean, then re-zeroes all state.
__global__ void k_select(float* __restrict__ out, unsigned k) {
    __shared__ unsigned wTotC[32], wExC[32];
    __shared__ float    wTotS[32], wExS[32];
    __shared__ unsigned sTotWinC;
    __shared__ float    sTotWinS;

    int t = threadIdx.x, lane = t & 31, wid = t >> 5;

    uint4  c4 = *(const uint4*) &g_cnt[4 * t];
    float4 s4 = *(const float4*)&g_sum[4 * t];
    unsigned cb[4] = {c4.x, c4.y, c4.z, c4.w};
    float    sb[4] = {s4.x, s4.y, s4.z, s4.w};

    unsigned cntHi = g_hiCnt, cntLo = g_loCnt;
    float    sumHi = g_hiSum, sumLo = g_loSum;

    unsigned pc = cb[0] + cb[1] + cb[2] + cb[3];
    float    ps = sb[0] + sb[1] + sb[2] + sb[3];

    unsigned ic = pc; float is = ps;
    warp_suffix(ic, is);                         // lanes >= lane, inclusive
    if (lane == 0) { wTotC[wid] = ic; wTotS[wid] = is; }
    __syncthreads();
    if (wid == 0) {
        unsigned cc = wTotC[lane]; float ss = wTotS[lane];
        unsigned i2 = cc; float i2s = ss;
        warp_suffix(i2, i2s);
        wExC[lane] = i2 - cc;                    // warps strictly above
        wExS[lane] = i2s - ss;
        if (lane == 0) { sTotWinC = i2; sTotWinS = i2s; }
    }
    __syncthreads();

    unsigned inclT  = ic + wExC[wid];            // threads >= t
    float    inclTS = is + wExS[wid];
    unsigned aboveT = inclT - pc;                // threads > t
    float    aboveS = inclTS - ps;
    unsigned totWinC = sTotWinC;
    float    totWinS = sTotWinS;

    if (cntHi >= k) {
        // k-th value is inside the hi-overflow bin (degenerate)
        if (t == 0)
            out[0] = (float)((double)sumHi / (double)cntHi);
    } else {
        unsigned kk = k - cntHi;
        if (totWinC < kk) {
            // window exhausted: dip into lo-overflow proportionally
            if (t == 0) {
                unsigned rem = kk - totWinC;
                double lo = (cntLo > 0u)
                    ? (double)sumLo * ((double)(rem < cntLo ? rem : cntLo) / (double)cntLo)
                    : 0.0;
                out[0] = (float)(((double)sumHi + (double)totWinS + lo) / (double)k);
            }
        } else if (aboveT < kk && inclT >= kk) { // exactly one thread
            unsigned above = aboveT; float asum = aboveS;
            #pragma unroll
            for (int j = 3; j >= 0; j--) {       // high key -> low key
                unsigned h = cb[j];
                if (above < kk && above + h >= kk) {
                    unsigned ties = kk - above;  // >= 1, <= h
                    double total = (double)sumHi + (double)asum
                                 + (double)sb[j] * ((double)ties / (double)h);
                    out[0] = (float)(total / (double)k);
                }
                above += h; asum += sb[j];
            }
        }
    }

    // re-zero all state for the next invocation (graph replay determinism)
    __syncthreads();
    *(uint4*) &g_cnt[4 * t] = make_uint4(0u, 0u, 0u, 0u);
    *(float4*)&g_sum[4 * t] = make_float4(0.f, 0.f, 0.f, 0.f);
    if (t == 0) { g_loCnt = 0u; g_hiCnt = 0u; g_loSum = 0.0f; g_hiSum = 0.0f; }
}

// ---------------------------------------------------------------------------
extern "C" void kernel_launch(void* const* d_in, const int* in_sizes, int n_in,
                              void* d_out, int out_size) {
    const float*     x   = (const float*)d_in[0];
    const long long* tgt = (const long long*)d_in[1];
    float*           out = (float*)d_out;

    int N = in_sizes[1];
    int C = in_sizes[0] / N;
    unsigned k = (unsigned)(0.7 * (double)N);
    if (k < 1u) k = 1u;

    if (C == 128 && (N & 3) == 0) {
        int threads = 512;
        int blocks  = 296;                        // 148 SMs x 2 (persistent)
        int warpsNeeded = (N + 3) / 4;
        int maxBlocks = (warpsNeeded + 15) / 16;
        if (blocks > maxBlocks) blocks = maxBlocks;
        int totalWarps = blocks * (threads / 32);
        k_loss128<<<blocks, threads>>>((const float4*)x, tgt, N, totalWarps);
    } else {
        k_loss_generic<<<(N + 255) / 256, 256>>>(x, tgt, N, C);
    }

    k_select<<<1, 1024>>>(out, k);
}

// round 11
// speedup vs baseline: 1.0317x; 1.0317x over previous
#include <cuda_runtime.h>
#include <cstdint>
#include <math.h>

// ---------------------------------------------------------------------------
// topk cross-entropy: mean of top-70% per-row NLL losses.
//   loss[i] = log(sum_c exp(x[i,c])) - x[i, target[i]]   (>= 0)
// Single fused kernel: per-block smem-privatized 4096-bin histogram
// (keys = top16 float bits, window [2^-7, 2^25)) + lo/hi overflow scalars,
// global flush, then the LAST block (ticket) runs the hierarchical suffix
// scan, writes the answer, and re-zeroes all state for the next replay.
// Boundary bin credited proportionally (bin rel. width 2^-7 -> ~4e-5 err).
// ---------------------------------------------------------------------------

#define FULLMASK 0xFFFFFFFFu
#define WIN_LO   0x3C00u          // key of 2^-7
#define WIN_BINS 4096

__device__ unsigned g_cnt[WIN_BINS];
__device__ float    g_sum[WIN_BINS];
__device__ unsigned g_loCnt, g_hiCnt;
__device__ float    g_loSum, g_hiSum;
__device__ unsigned g_ticket;

__device__ __forceinline__ float warp_sum(float v) {
    #pragma unroll
    for (int o = 16; o; o >>= 1) v += __shfl_xor_sync(FULLMASK, v, o);
    return v;
}

// inclusive suffix scan within a warp (sum over lanes >= lane)
__device__ __forceinline__ void warp_suffix(unsigned& c, float& s) {
    int lane = threadIdx.x & 31;
    #pragma unroll
    for (int o = 1; o < 32; o <<= 1) {
        unsigned tc = __shfl_down_sync(FULLMASK, c, o);
        float    ts = __shfl_down_sync(FULLMASK, s, o);
        if (lane + o < 32) { c += tc; s += ts; }
    }
}

__device__ __forceinline__ float row_exp_sum(float4 v) {
    return __expf(v.x) + __expf(v.y) + __expf(v.z) + __expf(v.w);
}

__device__ __forceinline__ float sel4(float4 v, int sub) {
    return sub == 0 ? v.x : sub == 1 ? v.y : sub == 2 ? v.z : v.w;
}

// ---------------------------------------------------------------------------
// Selection + state reset, executed by 512 threads (8 bins/thread, 16 warps).
// Reads histogram via volatile (L2-coherent after threadfence/ticket acquire).
// ---------------------------------------------------------------------------
__device__ void do_select_and_reset(float* __restrict__ out, unsigned k) {
    __shared__ unsigned selTotC[32], selExC[32];
    __shared__ float    selTotS[32], selExS[32];
    __shared__ unsigned selWinC;
    __shared__ float    selWinS;

    int t = threadIdx.x, lane = t & 31, wid = t >> 5;   // 16 warps

    volatile unsigned* vc = g_cnt;
    volatile float*    vs = g_sum;

    unsigned cb[8]; float sb[8];
    #pragma unroll
    for (int j = 0; j < 8; j++) { cb[j] = vc[8 * t + j]; sb[j] = vs[8 * t + j]; }

    unsigned cntHi = *(volatile unsigned*)&g_hiCnt;
    unsigned cntLo = *(volatile unsigned*)&g_loCnt;
    float    sumHi = *(volatile float*)&g_hiSum;
    float    sumLo = *(volatile float*)&g_loSum;

    unsigned pc = 0; float ps = 0.0f;
    #pragma unroll
    for (int j = 0; j < 8; j++) { pc += cb[j]; ps += sb[j]; }

    unsigned ic = pc; float is = ps;
    warp_suffix(ic, is);                          // lanes >= lane
    if (lane == 0) { selTotC[wid] = ic; selTotS[wid] = is; }
    __syncthreads();
    if (wid == 0) {
        unsigned cc = (lane < 16) ? selTotC[lane] : 0u;
        float    ss = (lane < 16) ? selTotS[lane] : 0.0f;
        unsigned i2 = cc; float i2s = ss;
        warp_suffix(i2, i2s);
        selExC[lane] = i2 - cc;                   // warps strictly above
        selExS[lane] = i2s - ss;
        if (lane == 0) { selWinC = i2; selWinS = i2s; }
    }
    __syncthreads();

    unsigned inclT  = ic + selExC[wid];           // threads >= t
    float    inclTS = is + selExS[wid];
    unsigned aboveT = inclT - pc;                 // threads > t
    float    aboveS = inclTS - ps;
    unsigned totWinC = selWinC;
    float    totWinS = selWinS;

    if (cntHi >= k) {
        if (t == 0) out[0] = (float)((double)sumHi / (double)cntHi);
    } else {
        unsigned kk = k - cntHi;
        if (totWinC < kk) {
            if (t == 0) {
                unsigned rem = kk - totWinC;
                double lo = (cntLo > 0u)
                    ? (double)sumLo * ((double)(rem < cntLo ? rem : cntLo) / (double)cntLo)
                    : 0.0;
                out[0] = (float)(((double)sumHi + (double)totWinS + lo) / (double)k);
            }
        } else if (aboveT < kk && inclT >= kk) {  // exactly one thread
            unsigned above = aboveT; float asum = aboveS;
            #pragma unroll
            for (int j = 7; j >= 0; j--) {        // high key -> low key
                unsigned h = cb[j];
                if (above < kk && above + h >= kk) {
                    unsigned ties = kk - above;
                    double total = (double)sumHi + (double)asum
                                 + (double)sb[j] * ((double)ties / (double)h);
                    out[0] = (float)(total / (double)k);
                }
                above += h; asum += sb[j];
            }
        }
    }

    __syncthreads();
    // re-zero all state for the next graph replay
    #pragma unroll
    for (int j = 0; j < 8; j++) { g_cnt[8 * t + j] = 0u; g_sum[8 * t + j] = 0.0f; }
    if (t == 0) {
        g_loCnt = 0u; g_hiCnt = 0u; g_loSum = 0.0f; g_hiSum = 0.0f;
        __threadfence();
        g_ticket = 0u;
    }
}

// ---------------------------------------------------------------------------
// Fused kernel: persistent loss+histogram, last block selects & resets.
// ---------------------------------------------------------------------------
__global__ void __launch_bounds__(512, 2)
k_fused(const float4* __restrict__ x,
        const long long* __restrict__ tgt,
        float* __restrict__ out,
        int N, int totalWarps, unsigned k, int numBlocks) {
    __shared__ unsigned scnt[WIN_BINS];
    __shared__ float    ssum[WIN_BINS];
    __shared__ unsigned sLoC, sHiC, sLast;
    __shared__ float    sLoS, sHiS;

    int tid  = threadIdx.x;
    int gw   = (blockIdx.x * blockDim.x + tid) >> 5;
    int lane = tid & 31;

    #pragma unroll
    for (int b = tid; b < WIN_BINS; b += 512) { scnt[b] = 0u; ssum[b] = 0.0f; }
    if (tid == 0) { sLoC = 0u; sHiC = 0u; sLoS = 0.0f; sHiS = 0.0f; }
    __syncthreads();

    int stride = totalWarps * 4;
    int row0   = gw * 4;

    if (row0 < N) {
        // software pipeline: prefetch next iteration's rows
        float4 v0 = __ldg(&x[(size_t)(row0 + 0) * 32 + lane]);
        float4 v1 = __ldg(&x[(size_t)(row0 + 1) * 32 + lane]);
        float4 v2 = __ldg(&x[(size_t)(row0 + 2) * 32 + lane]);
        float4 v3 = __ldg(&x[(size_t)(row0 + 3) * 32 + lane]);

        for (; row0 < N; row0 += stride) {
            int nrow = row0 + stride;
            float4 n0, n1, n2, n3;
            if (nrow < N) {
                n0 = __ldg(&x[(size_t)(nrow + 0) * 32 + lane]);
                n1 = __ldg(&x[(size_t)(nrow + 1) * 32 + lane]);
                n2 = __ldg(&x[(size_t)(nrow + 2) * 32 + lane]);
                n3 = __ldg(&x[(size_t)(nrow + 3) * 32 + lane]);
            }
            int t0 = (int)__ldg(&tgt[row0 + 0]);
            int t1 = (int)__ldg(&tgt[row0 + 1]);
            int t2 = (int)__ldg(&tgt[row0 + 2]);
            int t3 = (int)__ldg(&tgt[row0 + 3]);

            float s0 = row_exp_sum(v0);
            float s1 = row_exp_sum(v1);
            float s2 = row_exp_sum(v2);
            float s3 = row_exp_sum(v3);
            s0 = warp_sum(s0); s1 = warp_sum(s1); s2 = warp_sum(s2); s3 = warp_sum(s3);

            float xt0 = __shfl_sync(FULLMASK, sel4(v0, t0 & 3), t0 >> 2);
            float xt1 = __shfl_sync(FULLMASK, sel4(v1, t1 & 3), t1 >> 2);
            float xt2 = __shfl_sync(FULLMASK, sel4(v2, t2 & 3), t2 >> 2);
            float xt3 = __shfl_sync(FULLMASK, sel4(v3, t3 & 3), t3 >> 2);

            float l0 = fmaxf(__logf(s0) - xt0, 0.0f);
            float l1 = fmaxf(__logf(s1) - xt1, 0.0f);
            float l2 = fmaxf(__logf(s2) - xt2, 0.0f);
            float l3 = fmaxf(__logf(s3) - xt3, 0.0f);

            if (lane < 4) {
                float L = lane == 0 ? l0 : lane == 1 ? l1 : lane == 2 ? l2 : l3;
                unsigned key = __float_as_uint(L) >> 16;
                unsigned w   = key - WIN_LO;
                if (w < WIN_BINS) {
                    atomicAdd(&scnt[w], 1u);
                    atomicAdd(&ssum[w], L);
                } else if (key < WIN_LO) {
                    atomicAdd(&sLoC, 1u); atomicAdd(&sLoS, L);
                } else {
                    atomicAdd(&sHiC, 1u); atomicAdd(&sHiS, L);
                }
            }

            v0 = n0; v1 = n1; v2 = n2; v3 = n3;
        }
    }

    __syncthreads();
    // flush private histogram to global
    for (int b = tid; b < WIN_BINS; b += 512) {
        unsigned c = scnt[b];
        if (c) {
            atomicAdd(&g_cnt[b], c);
            atomicAdd(&g_sum[b], ssum[b]);
        }
    }
    if (tid == 0) {
        if (sLoC) { atomicAdd(&g_loCnt, sLoC); atomicAdd(&g_loSum, sLoS); }
        if (sHiC) { atomicAdd(&g_hiCnt, sHiC); atomicAdd(&g_hiSum, sHiS); }
    }

    // ticket: last block to finish does the selection
    __syncthreads();
    if (tid == 0) {
        __threadfence();
        unsigned rank = atomicAdd(&g_ticket, 1u);
        sLast = (rank == (unsigned)numBlocks - 1u) ? 1u : 0u;
    }
    __syncthreads();
    if (sLast) {
        __threadfence();
        do_select_and_reset(out, k);
    }
}

// ---------------------------------------------------------------------------
// Fallback path (C != 128 or N % 4 != 0) — safety only.
// ---------------------------------------------------------------------------
__global__ void k_loss_generic(const float* __restrict__ x,
                               const long long* __restrict__ tgt, int N, int C) {
    int r = blockIdx.x * blockDim.x + threadIdx.x;
    if (r >= N) return;
    const float* row = x + (size_t)r * C;
    float m = -INFINITY;
    for (int c = 0; c < C; c++) m = fmaxf(m, row[c]);
    float s = 0.0f;
    for (int c = 0; c < C; c++) s += __expf(row[c] - m);
    float loss = fmaxf(m + __logf(s) - row[(int)tgt[r]], 0.0f);
    unsigned key = __float_as_uint(loss) >> 16;
    unsigned w   = key - WIN_LO;
    if (w < WIN_BINS) { atomicAdd(&g_cnt[w], 1u); atomicAdd(&g_sum[w], loss); }
    else if (key < WIN_LO) { atomicAdd(&g_loCnt, 1u); atomicAdd(&g_loSum, loss); }
    else                   { atomicAdd(&g_hiCnt, 1u); atomicAdd(&g_hiSum, loss); }
}

__global__ void k_select_standalone(float* __restrict__ out, unsigned k) {
    do_select_and_reset(out, k);
}

// ---------------------------------------------------------------------------
extern "C" void kernel_launch(void* const* d_in, const int* in_sizes, int n_in,
                              void* d_out, int out_size) {
    const float*     x   = (const float*)d_in[0];
    const long long* tgt = (const long long*)d_in[1];
    float*           out = (float*)d_out;

    int N = in_sizes[1];
    int C = in_sizes[0] / N;
    unsigned k = (unsigned)(0.7 * (double)N);
    if (k < 1u) k = 1u;

    if (C == 128 && (N & 3) == 0) {
        int threads = 512;
        int blocks  = 296;                        // 148 SMs x 2 (persistent)
        int warpsNeeded = (N + 3) / 4;
        int maxBlocks = (warpsNeeded + 15) / 16;
        if (blocks > maxBlocks) blocks = maxBlocks;
        if (blocks < 1) blocks = 1;
        int totalWarps = blocks * (threads / 32);
        k_fused<<<blocks, threads>>>((const float4*)x, tgt, out, N, totalWarps, k, blocks);
    } else {
        k_loss_generic<<<(N + 255) / 256, 256>>>(x, tgt, N, C);
        k_select_standalone<<<1, 512>>>(out, k);
    }
}

// round 14
// speedup vs baseline: 1.0589x; 1.0264x over previous
#include <cuda_runtime.h>
#include <cstdint>
#include <math.h>

// ---------------------------------------------------------------------------
// topk cross-entropy: mean of top-70% per-row NLL losses.
//   loss[i] = log(sum_c exp(x[i,c])) - x[i, target[i]]   (>= 0)
// Single fused kernel: 8 rows/warp-iteration (MLP=8), warp row-sums via
// integer redux.sync (fixed-point 2^18, rel err ~3e-7), per-block
// smem-privatized 4096-bin histogram (keys = top16 float bits, window
// [2^-7, 2^25)) + lo/hi overflow scalars; last block (ticket) runs the
// hierarchical suffix scan, writes the answer, and re-zeroes all state.
// Boundary bin credited proportionally (~4e-5 err on the mean).
// ---------------------------------------------------------------------------

#define FULLMASK 0xFFFFFFFFu
#define WIN_LO   0x3C00u          // key of 2^-7
#define WIN_BINS 4096
#define FXP_SCALE 262144.0f       // 2^18
#define LOG_FXP   12.476649250079015f   // 18 * ln(2)

__device__ unsigned g_cnt[WIN_BINS];
__device__ float    g_sum[WIN_BINS];
__device__ unsigned g_loCnt, g_hiCnt;
__device__ float    g_loSum, g_hiSum;
__device__ unsigned g_ticket;

// inclusive suffix scan within a warp (sum over lanes >= lane)
__device__ __forceinline__ void warp_suffix(unsigned& c, float& s) {
    int lane = threadIdx.x & 31;
    #pragma unroll
    for (int o = 1; o < 32; o <<= 1) {
        unsigned tc = __shfl_down_sync(FULLMASK, c, o);
        float    ts = __shfl_down_sync(FULLMASK, s, o);
        if (lane + o < 32) { c += tc; s += ts; }
    }
}

__device__ __forceinline__ float row_exp_sum(float4 v) {
    return (__expf(v.x) + __expf(v.y)) + (__expf(v.z) + __expf(v.w));
}

__device__ __forceinline__ float sel4(float4 v, int sub) {
    return sub == 0 ? v.x : sub == 1 ? v.y : sub == 2 ? v.z : v.w;
}

// warp row-sum: fixed-point + one redux.sync.add.u32
__device__ __forceinline__ float warp_sum_fxp(float partial) {
    unsigned q = __reduce_add_sync(FULLMASK, (unsigned)(partial * FXP_SCALE));
    return (float)q;            // log(s_true) = __logf(q) - LOG_FXP
}

// ---------------------------------------------------------------------------
// Selection + state reset, executed by 512 threads (8 bins/thread, 16 warps).
// ---------------------------------------------------------------------------
__device__ void do_select_and_reset(float* __restrict__ out, unsigned k) {
    __shared__ unsigned selTotC[32], selExC[32];
    __shared__ float    selTotS[32], selExS[32];
    __shared__ unsigned selWinC;
    __shared__ float    selWinS;

    int t = threadIdx.x, lane = t & 31, wid = t >> 5;   // 16 warps

    volatile unsigned* vc = g_cnt;
    volatile float*    vs = g_sum;

    unsigned cb[8]; float sb[8];
    #pragma unroll
    for (int j = 0; j < 8; j++) { cb[j] = vc[8 * t + j]; sb[j] = vs[8 * t + j]; }

    unsigned cntHi = *(volatile unsigned*)&g_hiCnt;
    unsigned cntLo = *(volatile unsigned*)&g_loCnt;
    float    sumHi = *(volatile float*)&g_hiSum;
    float    sumLo = *(volatile float*)&g_loSum;

    unsigned pc = 0; float ps = 0.0f;
    #pragma unroll
    for (int j = 0; j < 8; j++) { pc += cb[j]; ps += sb[j]; }

    unsigned ic = pc; float is = ps;
    warp_suffix(ic, is);                          // lanes >= lane
    if (lane == 0) { selTotC[wid] = ic; selTotS[wid] = is; }
    __syncthreads();
    if (wid == 0) {
        unsigned cc = (lane < 16) ? selTotC[lane] : 0u;
        float    ss = (lane < 16) ? selTotS[lane] : 0.0f;
        unsigned i2 = cc; float i2s = ss;
        warp_suffix(i2, i2s);
        selExC[lane] = i2 - cc;                   // warps strictly above
        selExS[lane] = i2s - ss;
        if (lane == 0) { selWinC = i2; selWinS = i2s; }
    }
    __syncthreads();

    unsigned inclT  = ic + selExC[wid];           // threads >= t
    float    inclTS = is + selExS[wid];
    unsigned aboveT = inclT - pc;                 // threads > t
    float    aboveS = inclTS - ps;
    unsigned totWinC = selWinC;
    float    totWinS = selWinS;

    if (cntHi >= k) {
        if (t == 0) out[0] = (float)((double)sumHi / (double)cntHi);
    } else {
        unsigned kk = k - cntHi;
        if (totWinC < kk) {
            if (t == 0) {
                unsigned rem = kk - totWinC;
                double lo = (cntLo > 0u)
                    ? (double)sumLo * ((double)(rem < cntLo ? rem : cntLo) / (double)cntLo)
                    : 0.0;
                out[0] = (float)(((double)sumHi + (double)totWinS + lo) / (double)k);
            }
        } else if (aboveT < kk && inclT >= kk) {  // exactly one thread
            unsigned above = aboveT; float asum = aboveS;
            #pragma unroll
            for (int j = 7; j >= 0; j--) {        // high key -> low key
                unsigned h = cb[j];
                if (above < kk && above + h >= kk) {
                    unsigned ties = kk - above;
                    double total = (double)sumHi + (double)asum
                                 + (double)sb[j] * ((double)ties / (double)h);
                    out[0] = (float)(total / (double)k);
                }
                above += h; asum += sb[j];
            }
        }
    }

    __syncthreads();
    // re-zero all state for the next graph replay
    #pragma unroll
    for (int j = 0; j < 8; j++) { g_cnt[8 * t + j] = 0u; g_sum[8 * t + j] = 0.0f; }
    if (t == 0) {
        g_loCnt = 0u; g_hiCnt = 0u; g_loSum = 0.0f; g_hiSum = 0.0f;
        __threadfence();
        g_ticket = 0u;
    }
}

// ---------------------------------------------------------------------------
// Fused kernel: persistent loss+histogram (8 rows/warp-iter), last block
// selects & resets.
// ---------------------------------------------------------------------------
__global__ void __launch_bounds__(512, 2)
k_fused(const float4* __restrict__ x,
        const long long* __restrict__ tgt,
        float* __restrict__ out,
        int N, int totalWarps, unsigned k, int numBlocks) {
    __shared__ unsigned scnt[WIN_BINS];
    __shared__ float    ssum[WIN_BINS];
    __shared__ unsigned sLoC, sHiC, sLast;
    __shared__ float    sLoS, sHiS;

    int tid  = threadIdx.x;
    int gw   = (blockIdx.x * blockDim.x + tid) >> 5;
    int lane = tid & 31;

    #pragma unroll
    for (int b = tid; b < WIN_BINS; b += 512) { scnt[b] = 0u; ssum[b] = 0.0f; }
    if (tid == 0) { sLoC = 0u; sHiC = 0u; sLoS = 0.0f; sHiS = 0.0f; }
    __syncthreads();

    int stride = totalWarps * 8;

    for (int row0 = gw * 8; row0 < N; row0 += stride) {
        const float4* base = x + (size_t)row0 * 32 + lane;
        // 8 independent 128-bit loads in flight per thread (const offsets)
        float4 v0 = __ldg(base + 0 * 32);
        float4 v1 = __ldg(base + 1 * 32);
        float4 v2 = __ldg(base + 2 * 32);
        float4 v3 = __ldg(base + 3 * 32);
        float4 v4 = __ldg(base + 4 * 32);
        float4 v5 = __ldg(base + 5 * 32);
        float4 v6 = __ldg(base + 6 * 32);
        float4 v7 = __ldg(base + 7 * 32);
        const long long* tb = tgt + row0;
        int t0 = (int)__ldg(tb + 0);
        int t1 = (int)__ldg(tb + 1);
        int t2 = (int)__ldg(tb + 2);
        int t3 = (int)__ldg(tb + 3);
        int t4 = (int)__ldg(tb + 4);
        int t5 = (int)__ldg(tb + 5);
        int t6 = (int)__ldg(tb + 6);
        int t7 = (int)__ldg(tb + 7);

        // one integer redux per row replaces the 5-step fp butterfly
        float s0 = warp_sum_fxp(row_exp_sum(v0));
        float s1 = warp_sum_fxp(row_exp_sum(v1));
        float s2 = warp_sum_fxp(row_exp_sum(v2));
        float s3 = warp_sum_fxp(row_exp_sum(v3));
        float s4 = warp_sum_fxp(row_exp_sum(v4));
        float s5 = warp_sum_fxp(row_exp_sum(v5));
        float s6 = warp_sum_fxp(row_exp_sum(v6));
        float s7 = warp_sum_fxp(row_exp_sum(v7));

        float xt0 = __shfl_sync(FULLMASK, sel4(v0, t0 & 3), t0 >> 2);
        float xt1 = __shfl_sync(FULLMASK, sel4(v1, t1 & 3), t1 >> 2);
        float xt2 = __shfl_sync(FULLMASK, sel4(v2, t2 & 3), t2 >> 2);
        float xt3 = __shfl_sync(FULLMASK, sel4(v3, t3 & 3), t3 >> 2);
        float xt4 = __shfl_sync(FULLMASK, sel4(v4, t4 & 3), t4 >> 2);
        float xt5 = __shfl_sync(FULLMASK, sel4(v5, t5 & 3), t5 >> 2);
        float xt6 = __shfl_sync(FULLMASK, sel4(v6, t6 & 3), t6 >> 2);
        float xt7 = __shfl_sync(FULLMASK, sel4(v7, t7 & 3), t7 >> 2);

        float l0 = fmaxf(__logf(s0) - LOG_FXP - xt0, 0.0f);
        float l1 = fmaxf(__logf(s1) - LOG_FXP - xt1, 0.0f);
        float l2 = fmaxf(__logf(s2) - LOG_FXP - xt2, 0.0f);
        float l3 = fmaxf(__logf(s3) - LOG_FXP - xt3, 0.0f);
        float l4 = fmaxf(__logf(s4) - LOG_FXP - xt4, 0.0f);
        float l5 = fmaxf(__logf(s5) - LOG_FXP - xt5, 0.0f);
        float l6 = fmaxf(__logf(s6) - LOG_FXP - xt6, 0.0f);
        float l7 = fmaxf(__logf(s7) - LOG_FXP - xt7, 0.0f);

        if (lane < 8) {
            // select this lane's row via a 3-level tree (7 SELs)
            float La = (lane & 1) ? l1 : l0;
            float Lb = (lane & 1) ? l3 : l2;
            float Lc = (lane & 1) ? l5 : l4;
            float Ld = (lane & 1) ? l7 : l6;
            float Le = (lane & 2) ? Lb : La;
            float Lf = (lane & 2) ? Ld : Lc;
            float L  = (lane & 4) ? Lf : Le;
            unsigned key = __float_as_uint(L) >> 16;
            unsigned w   = key - WIN_LO;
            if (w < WIN_BINS) {
                atomicAdd(&scnt[w], 1u);
                atomicAdd(&ssum[w], L);
            } else if (key < WIN_LO) {
                atomicAdd(&sLoC, 1u); atomicAdd(&sLoS, L);
            } else {
                atomicAdd(&sHiC, 1u); atomicAdd(&sHiS, L);
            }
        }
    }

    __syncthreads();
    // flush private histogram to global
    for (int b = tid; b < WIN_BINS; b += 512) {
        unsigned c = scnt[b];
        if (c) {
            atomicAdd(&g_cnt[b], c);
            atomicAdd(&g_sum[b], ssum[b]);
        }
    }
    if (tid == 0) {
        if (sLoC) { atomicAdd(&g_loCnt, sLoC); atomicAdd(&g_loSum, sLoS); }
        if (sHiC) { atomicAdd(&g_hiCnt, sHiC); atomicAdd(&g_hiSum, sHiS); }
    }

    // ticket: last block to finish does the selection
    __syncthreads();
    if (tid == 0) {
        __threadfence();
        unsigned rank = atomicAdd(&g_ticket, 1u);
        sLast = (rank == (unsigned)numBlocks - 1u) ? 1u : 0u;
    }
    __syncthreads();
    if (sLast) {
        __threadfence();
        do_select_and_reset(out, k);
    }
}

// ---------------------------------------------------------------------------
// Fallback path (C != 128 or N % 8 != 0) — safety only.
// ---------------------------------------------------------------------------
__global__ void k_loss_generic(const float* __restrict__ x,
                               const long long* __restrict__ tgt, int N, int C) {
    int r = blockIdx.x * blockDim.x + threadIdx.x;
    if (r >= N) return;
    const float* row = x + (size_t)r * C;
    float m = -INFINITY;
    for (int c = 0; c < C; c++) m = fmaxf(m, row[c]);
    float s = 0.0f;
    for (int c = 0; c < C; c++) s += __expf(row[c] - m);
    float loss = fmaxf(m + __logf(s) - row[(int)tgt[r]], 0.0f);
    unsigned key = __float_as_uint(loss) >> 16;
    unsigned w   = key - WIN_LO;
    if (w < WIN_BINS) { atomicAdd(&g_cnt[w], 1u); atomicAdd(&g_sum[w], loss); }
    else if (key < WIN_LO) { atomicAdd(&g_loCnt, 1u); atomicAdd(&g_loSum, loss); }
    else                   { atomicAdd(&g_hiCnt, 1u); atomicAdd(&g_hiSum, loss); }
}

__global__ void k_select_standalone(float* __restrict__ out, unsigned k) {
    do_select_and_reset(out, k);
}

// ---------------------------------------------------------------------------
extern "C" void kernel_launch(void* const* d_in, const int* in_sizes, int n_in,
                              void* d_out, int out_size) {
    const float*     x   = (const float*)d_in[0];
    const long long* tgt = (const long long*)d_in[1];
    float*           out = (float*)d_out;

    int N = in_sizes[1];
    int C = in_sizes[0] / N;
    unsigned k = (unsigned)(0.7 * (double)N);
    if (k < 1u) k = 1u;

    if (C == 128 && (N & 7) == 0) {
        int threads = 512;
        int blocks  = 296;                        // 148 SMs x 2 (persistent)
        int warpsNeeded = N / 8;
        int maxBlocks = (warpsNeeded + 15) / 16;
        if (blocks > maxBlocks) blocks = maxBlocks;
        if (blocks < 1) blocks = 1;
        int totalWarps = blocks * (threads / 32);
        k_fused<<<blocks, threads>>>((const float4*)x, tgt, out, N, totalWarps, k, blocks);
    } else {
        k_loss_generic<<<(N + 255) / 256, 256>>>(x, tgt, N, C);
        k_select_standalone<<<1, 512>>>(out, k);
    }
}